// round 2
// baseline (speedup 1.0000x reference)
#include <cuda_runtime.h>

#define BATCH 65536
#define SEQ 54
#define DIM 6
#define NB 8
#define GG 4                 // batch items per CTA
#define TPB (GG * SEQ)       // 216 threads

__global__ void __launch_bounds__(TPB, 2) rubik_kernel(
    const float* __restrict__ x,
    const float* __restrict__ embed_w, const float* __restrict__ embed_b,
    const float* __restrict__ fc1_w,   const float* __restrict__ fc1_b,
    const float* __restrict__ ln_g,    const float* __restrict__ ln_b,
    const float* __restrict__ ipw,     const float* __restrict__ ipb,
    const float* __restrict__ outw,    const float* __restrict__ outb,
    const float* __restrict__ value_w, const float* __restrict__ value_b,
    const float* __restrict__ policy_w,const float* __restrict__ policy_b,
    float* __restrict__ out)
{
    __shared__ __align__(16) float s_ew[DIM][8];
    __shared__ float s_eb[8];
    __shared__ __align__(16) float s_fw[NB][DIM][8];
    __shared__ float s_fb[NB][8];
    __shared__ float s_g [NB][8];
    __shared__ float s_bb[NB][8];
    __shared__ __align__(16) float s_iw[NB][3*DIM][8];
    __shared__ float s_ib[NB][20];
    __shared__ __align__(16) float s_ow[NB][DIM][8];
    __shared__ float s_ob[NB][8];
    __shared__ __align__(16) float s_k[GG][SEQ][8];
    __shared__ __align__(16) float s_v[GG][SEQ][8];
    __shared__ float s_lg[GG][16];

    const int tid = threadIdx.x;

    // ---- cooperative weight staging (padded rows of 8 for LDS.128) ----
    for (int i = tid; i < 36;     i += TPB) s_ew[i/6][i%6] = embed_w[i];
    if (tid < 6) s_eb[tid] = embed_b[tid];
    for (int i = tid; i < NB*36;  i += TPB) s_fw[i/36][(i%36)/6][i%6] = fc1_w[i];
    for (int i = tid; i < NB*6;   i += TPB) s_fb[i/6][i%6] = fc1_b[i];
    for (int i = tid; i < NB*6;   i += TPB) s_g [i/6][i%6] = ln_g[i];
    for (int i = tid; i < NB*6;   i += TPB) s_bb[i/6][i%6] = ln_b[i];
    for (int i = tid; i < NB*108; i += TPB) s_iw[i/108][(i%108)/6][i%6] = ipw[i];
    for (int i = tid; i < NB*18;  i += TPB) s_ib[i/18][i%18] = ipb[i];
    for (int i = tid; i < NB*36;  i += TPB) s_ow[i/36][(i%36)/6][i%6] = outw[i];
    for (int i = tid; i < NB*6;   i += TPB) s_ob[i/6][i%6] = outb[i];
    __syncthreads();

    const int g    = tid / SEQ;        // item slot within CTA
    const int t    = tid - g * SEQ;    // token index
    const int item = blockIdx.x * GG + g;

    // ---- embed: h = x @ ew^T + eb ----
    float h[6];
    {
        const float* xp = x + (item * SEQ + t) * DIM;
        float xin[6];
        #pragma unroll
        for (int d = 0; d < 6; d++) xin[d] = xp[d];
        #pragma unroll
        for (int i = 0; i < 6; i++) {
            float acc = s_eb[i];
            #pragma unroll
            for (int j = 0; j < 6; j++) acc = fmaf(s_ew[i][j], xin[j], acc);
            h[i] = acc;
        }
    }

    const float4* k4  = reinterpret_cast<const float4*>(&s_k[g][0][0]);
    const float4* v4  = reinterpret_cast<const float4*>(&s_v[g][0][0]);
    float4* kme = reinterpret_cast<float4*>(&s_k[g][t][0]);
    float4* vme = reinterpret_cast<float4*>(&s_v[g][t][0]);

    const float ISQ = 0.40824829046386302f;   // 1/sqrt(DIM)

    for (int blk = 0; blk < NB; blk++) {
        // ---- fc1 + ELU ----
        float z[6];
        {
            const float4* w4 = reinterpret_cast<const float4*>(&s_fw[blk][0][0]);
            #pragma unroll
            for (int i = 0; i < 6; i++) {
                float4 a = w4[2*i]; float4 b = w4[2*i+1];
                float acc = s_fb[blk][i];
                acc = fmaf(a.x, h[0], acc); acc = fmaf(a.y, h[1], acc);
                acc = fmaf(a.z, h[2], acc); acc = fmaf(a.w, h[3], acc);
                acc = fmaf(b.x, h[4], acc); acc = fmaf(b.y, h[5], acc);
                z[i] = acc > 0.f ? acc : (__expf(acc) - 1.f);
            }
        }
        // ---- LayerNorm (biased var, eps 1e-5) ----
        {
            float mu = (z[0]+z[1]+z[2]+z[3]+z[4]+z[5]) * (1.f/6.f);
            float var = 0.f;
            #pragma unroll
            for (int i = 0; i < 6; i++) { float d = z[i] - mu; var = fmaf(d, d, var); }
            var *= (1.f/6.f);
            float rs = rsqrtf(var + 1e-5f);
            #pragma unroll
            for (int i = 0; i < 6; i++)
                z[i] = fmaf((z[i] - mu) * rs, s_g[blk][i], s_bb[blk][i]);
        }
        // ---- packed qkv projection (scale folded into q) ----
        float q[6], kk[6], vv[6];
        {
            const float4* w4 = reinterpret_cast<const float4*>(&s_iw[blk][0][0]);
            #pragma unroll
            for (int i = 0; i < 18; i++) {
                float4 a = w4[2*i]; float4 b = w4[2*i+1];
                float acc = s_ib[blk][i];
                acc = fmaf(a.x, z[0], acc); acc = fmaf(a.y, z[1], acc);
                acc = fmaf(a.z, z[2], acc); acc = fmaf(a.w, z[3], acc);
                acc = fmaf(b.x, z[4], acc); acc = fmaf(b.y, z[5], acc);
                if      (i < 6)  q[i]      = acc * ISQ;
                else if (i < 12) kk[i - 6] = acc;
                else             vv[i - 12] = acc;
            }
        }
        __syncthreads();   // prior-block k/v reads complete before overwrite
        kme[0] = make_float4(kk[0], kk[1], kk[2], kk[3]);
        kme[1] = make_float4(kk[4], kk[5], 0.f, 0.f);
        vme[0] = make_float4(vv[0], vv[1], vv[2], vv[3]);
        vme[1] = make_float4(vv[4], vv[5], 0.f, 0.f);
        __syncthreads();   // k/v visible to the whole item

        // ---- scores + running max ----
        float s[SEQ];
        float mx = -1e30f;
        #pragma unroll
        for (int kq = 0; kq < SEQ; kq++) {
            float4 a = k4[2*kq]; float4 b = k4[2*kq+1];
            float d = q[0] * a.x;
            d = fmaf(q[1], a.y, d); d = fmaf(q[2], a.z, d); d = fmaf(q[3], a.w, d);
            d = fmaf(q[4], b.x, d); d = fmaf(q[5], b.y, d);
            s[kq] = d;
            mx = fmaxf(mx, d);
        }
        // ---- softmax-weighted v accumulation ----
        float o0=0.f,o1=0.f,o2=0.f,o3=0.f,o4=0.f,o5=0.f,sum=0.f;
        #pragma unroll
        for (int kq = 0; kq < SEQ; kq++) {
            float e = __expf(s[kq] - mx);
            sum += e;
            float4 a = v4[2*kq]; float4 b = v4[2*kq+1];
            o0 = fmaf(e, a.x, o0); o1 = fmaf(e, a.y, o1); o2 = fmaf(e, a.z, o2);
            o3 = fmaf(e, a.w, o3); o4 = fmaf(e, b.x, o4); o5 = fmaf(e, b.y, o5);
        }
        float inv = 1.0f / sum;
        float o[6] = {o0*inv, o1*inv, o2*inv, o3*inv, o4*inv, o5*inv};

        // ---- out proj + ELU + residual ----
        {
            const float4* w4 = reinterpret_cast<const float4*>(&s_ow[blk][0][0]);
            #pragma unroll
            for (int i = 0; i < 6; i++) {
                float4 a = w4[2*i]; float4 b = w4[2*i+1];
                float acc = s_ob[blk][i];
                acc = fmaf(a.x, o[0], acc); acc = fmaf(a.y, o[1], acc);
                acc = fmaf(a.z, o[2], acc); acc = fmaf(a.w, o[3], acc);
                acc = fmaf(b.x, o[4], acc); acc = fmaf(b.y, o[5], acc);
                h[i] += (acc > 0.f ? acc : (__expf(acc) - 1.f));
            }
        }
    }

    // ---- heads: stage flattened f[324] into (reused) s_k, then 13 dot products ----
    __syncthreads();                 // last attention reads of s_k done
    float* f = &s_k[g][0][0];
    #pragma unroll
    for (int d = 0; d < 6; d++) f[t*6 + d] = h[d];
    __syncthreads();

    if (t < 13) {
        const float* w = (t < 12) ? (policy_w + t * (SEQ*DIM)) : value_w;
        float acc = (t < 12) ? policy_b[t] : value_b[0];
        const float4* w4 = reinterpret_cast<const float4*>(w);
        const float4* f4 = reinterpret_cast<const float4*>(f);
        #pragma unroll 9
        for (int i = 0; i < (SEQ*DIM)/4; i++) {   // 81 float4s
            float4 a = w4[i]; float4 b = f4[i];
            acc = fmaf(a.x, b.x, acc); acc = fmaf(a.y, b.y, acc);
            acc = fmaf(a.z, b.z, acc); acc = fmaf(a.w, b.w, acc);
        }
        s_lg[g][t] = acc;
    }
    __syncthreads();

    if (t == 12) out[item] = s_lg[g][12];                       // value head
    if (t < 12) {                                               // policy softmax
        float m = s_lg[g][0];
        #pragma unroll
        for (int j = 1; j < 12; j++) m = fmaxf(m, s_lg[g][j]);
        float sum = 0.f;
        #pragma unroll
        for (int j = 0; j < 12; j++) sum += __expf(s_lg[g][j] - m);
        out[BATCH + item*12 + t] = __expf(s_lg[g][t] - m) / sum;
    }
}

extern "C" void kernel_launch(void* const* d_in, const int* in_sizes, int n_in,
                              void* d_out, int out_size) {
    const float* x        = (const float*)d_in[0];
    const float* embed_w  = (const float*)d_in[1];
    const float* embed_b  = (const float*)d_in[2];
    const float* fc1_w    = (const float*)d_in[3];
    const float* fc1_b    = (const float*)d_in[4];
    const float* ln_g     = (const float*)d_in[5];
    const float* ln_b     = (const float*)d_in[6];
    const float* ipw      = (const float*)d_in[7];
    const float* ipb      = (const float*)d_in[8];
    const float* outw     = (const float*)d_in[9];
    const float* outb     = (const float*)d_in[10];
    const float* value_w  = (const float*)d_in[11];
    const float* value_b  = (const float*)d_in[12];
    const float* policy_w = (const float*)d_in[13];
    const float* policy_b = (const float*)d_in[14];
    float* out = (float*)d_out;

    rubik_kernel<<<BATCH / GG, TPB>>>(x, embed_w, embed_b, fc1_w, fc1_b,
                                      ln_g, ln_b, ipw, ipb, outw, outb,
                                      value_w, value_b, policy_w, policy_b, out);
}

// round 4
// speedup vs baseline: 1.5257x; 1.5257x over previous
#include <cuda_runtime.h>

#define BATCH 65536
#define SEQ 54
#define DIM 6
#define NB 8
#define TPI 27               // threads per item (2 queries each)
#define GG 8                 // items per CTA
#define TPB (GG * TPI)       // 216 threads
#define KV_STRIDE 664        // floats per item slot: 54*12 + 16 pad (bank shift, 16B aligned)

typedef unsigned long long u64;

__device__ __forceinline__ float ex2f(float x) {
    float r; asm("ex2.approx.ftz.f32 %0, %1;" : "=f"(r) : "f"(x)); return r;
}
__device__ __forceinline__ u64 fma2(u64 a, u64 b, u64 c) {
    u64 d; asm("fma.rn.f32x2 %0, %1, %2, %3;" : "=l"(d) : "l"(a), "l"(b), "l"(c)); return d;
}
__device__ __forceinline__ u64 mul2(u64 a, u64 b) {
    u64 d; asm("mul.rn.f32x2 %0, %1, %2;" : "=l"(d) : "l"(a), "l"(b)); return d;
}
__device__ __forceinline__ u64 pack2(float lo, float hi) {
    u64 d; asm("mov.b64 %0, {%1, %2};" : "=l"(d)
               : "r"(__float_as_uint(lo)), "r"(__float_as_uint(hi))); return d;
}
__device__ __forceinline__ float2 unpack2(u64 d) {
    unsigned lo, hi; asm("mov.b64 {%0, %1}, %2;" : "=r"(lo), "=r"(hi) : "l"(d));
    return make_float2(__uint_as_float(lo), __uint_as_float(hi));
}
__device__ __forceinline__ float eluf(float x) { return x > 0.f ? x : (__expf(x) - 1.f); }

__global__ void __launch_bounds__(TPB, 3) rubik_kernel(
    const float* __restrict__ x,
    const float* __restrict__ embed_w, const float* __restrict__ embed_b,
    const float* __restrict__ fc1_w,   const float* __restrict__ fc1_b,
    const float* __restrict__ ln_g,    const float* __restrict__ ln_b,
    const float* __restrict__ ipw,     const float* __restrict__ ipb,
    const float* __restrict__ outw,    const float* __restrict__ outb,
    const float* __restrict__ value_w, const float* __restrict__ value_b,
    const float* __restrict__ policy_w,const float* __restrict__ policy_b,
    float* __restrict__ out)
{
    __shared__ __align__(16) float s_ew[DIM][8];
    __shared__ float s_eb[8];
    __shared__ __align__(16) float s_fw[NB][DIM][8];
    __shared__ float s_fb[NB][8];
    __shared__ float s_g [NB][8];
    __shared__ float s_bb[NB][8];
    __shared__ __align__(16) float s_iw[NB][3*DIM][8];
    __shared__ float s_ib[NB][20];
    __shared__ __align__(16) float s_ow[NB][DIM][8];
    __shared__ float s_ob[NB][8];
    __shared__ __align__(16) float s_kv[GG * KV_STRIDE];
    __shared__ float s_lg[GG][16];

    const int tid = threadIdx.x;

    // ---- cooperative weight staging (padded rows of 8 for LDS.128) ----
    for (int i = tid; i < 36;     i += TPB) s_ew[i/6][i%6] = embed_w[i];
    if (tid < 6) s_eb[tid] = embed_b[tid];
    for (int i = tid; i < NB*36;  i += TPB) s_fw[i/36][(i%36)/6][i%6] = fc1_w[i];
    for (int i = tid; i < NB*6;   i += TPB) s_fb[i/6][i%6] = fc1_b[i];
    for (int i = tid; i < NB*6;   i += TPB) s_g [i/6][i%6] = ln_g[i];
    for (int i = tid; i < NB*6;   i += TPB) s_bb[i/6][i%6] = ln_b[i];
    for (int i = tid; i < NB*108; i += TPB) s_iw[i/108][(i%108)/6][i%6] = ipw[i];
    for (int i = tid; i < NB*18;  i += TPB) s_ib[i/18][i%18] = ipb[i];
    for (int i = tid; i < NB*36;  i += TPB) s_ow[i/36][(i%36)/6][i%6] = outw[i];
    for (int i = tid; i < NB*6;   i += TPB) s_ob[i/6][i%6] = outb[i];
    __syncthreads();

    const int g    = tid / TPI;        // item slot within CTA
    const int t    = tid - g * TPI;    // query-thread index, handles tokens t, t+27
    const int item = blockIdx.x * GG + g;
    float* kvbase = s_kv + g * KV_STRIDE;

    // fold softmax scale and log2(e) into q
    const float QS = 0.40824829046386302f * 1.4426950408889634f;

    // ---- embed: h = x @ ew^T + eb (2 tokens, weights hoisted) ----
    float h[2][6];
    {
        float xin[2][6];
        #pragma unroll
        for (int j = 0; j < 2; j++) {
            const float* xp = x + (item * SEQ + t + j * TPI) * DIM;
            #pragma unroll
            for (int d = 0; d < 6; d++) xin[j][d] = xp[d];
        }
        const float4* w4 = reinterpret_cast<const float4*>(&s_ew[0][0]);
        #pragma unroll
        for (int i = 0; i < 6; i++) {
            float4 a = w4[2*i]; float4 b = w4[2*i+1];
            float bias = s_eb[i];
            #pragma unroll
            for (int j = 0; j < 2; j++) {
                float acc = bias;
                acc = fmaf(a.x, xin[j][0], acc); acc = fmaf(a.y, xin[j][1], acc);
                acc = fmaf(a.z, xin[j][2], acc); acc = fmaf(a.w, xin[j][3], acc);
                acc = fmaf(b.x, xin[j][4], acc); acc = fmaf(b.y, xin[j][5], acc);
                h[j][i] = acc;
            }
        }
    }

    for (int blk = 0; blk < NB; blk++) {
        // ---- fc1 + ELU (weights hoisted across both tokens) ----
        float z[2][6];
        {
            const float4* w4 = reinterpret_cast<const float4*>(&s_fw[blk][0][0]);
            #pragma unroll
            for (int i = 0; i < 6; i++) {
                float4 a = w4[2*i]; float4 b = w4[2*i+1];
                float bias = s_fb[blk][i];
                #pragma unroll
                for (int j = 0; j < 2; j++) {
                    float acc = bias;
                    acc = fmaf(a.x, h[j][0], acc); acc = fmaf(a.y, h[j][1], acc);
                    acc = fmaf(a.z, h[j][2], acc); acc = fmaf(a.w, h[j][3], acc);
                    acc = fmaf(b.x, h[j][4], acc); acc = fmaf(b.y, h[j][5], acc);
                    z[j][i] = eluf(acc);
                }
            }
        }
        // ---- LayerNorm (biased var, eps 1e-5) ----
        #pragma unroll
        for (int j = 0; j < 2; j++) {
            float mu = (z[j][0]+z[j][1]+z[j][2]+z[j][3]+z[j][4]+z[j][5]) * (1.f/6.f);
            float var = 0.f;
            #pragma unroll
            for (int i = 0; i < 6; i++) { float d = z[j][i] - mu; var = fmaf(d, d, var); }
            var *= (1.f/6.f);
            float rs = rsqrtf(var + 1e-5f);
            #pragma unroll
            for (int i = 0; i < 6; i++)
                z[j][i] = fmaf((z[j][i] - mu) * rs, s_g[blk][i], s_bb[blk][i]);
        }
        // ---- packed qkv projection (softmax scale + log2e folded into q) ----
        float q[2][6], kk[2][6], vv[2][6];
        {
            const float4* w4 = reinterpret_cast<const float4*>(&s_iw[blk][0][0]);
            #pragma unroll
            for (int i = 0; i < 18; i++) {
                float4 a = w4[2*i]; float4 b = w4[2*i+1];
                float bias = s_ib[blk][i];
                #pragma unroll
                for (int j = 0; j < 2; j++) {
                    float acc = bias;
                    acc = fmaf(a.x, z[j][0], acc); acc = fmaf(a.y, z[j][1], acc);
                    acc = fmaf(a.z, z[j][2], acc); acc = fmaf(a.w, z[j][3], acc);
                    acc = fmaf(b.x, z[j][4], acc); acc = fmaf(b.y, z[j][5], acc);
                    if      (i < 6)  q[j][i]      = acc * QS;
                    else if (i < 12) kk[j][i - 6] = acc;
                    else             vv[j][i - 12] = acc;
                }
            }
        }
        __syncthreads();   // prior-block k/v reads complete before overwrite
        #pragma unroll
        for (int j = 0; j < 2; j++) {
            float4* r4 = reinterpret_cast<float4*>(kvbase + (t + j * TPI) * 12);
            r4[0] = make_float4(kk[j][0], kk[j][1], kk[j][2], kk[j][3]);
            r4[1] = make_float4(kk[j][4], kk[j][5], vv[j][0], vv[j][1]);
            r4[2] = make_float4(vv[j][2], vv[j][3], vv[j][4], vv[j][5]);
        }
        __syncthreads();   // k/v visible to the whole item

        // ---- fused single-pass attention (max-free softmax, packed f32x2) ----
        u64 qp[2][3];
        #pragma unroll
        for (int j = 0; j < 2; j++)
            #pragma unroll
            for (int p = 0; p < 3; p++)
                qp[j][p] = pack2(q[j][2*p], q[j][2*p+1]);

        u64 o[2][3] = {{0ull,0ull,0ull},{0ull,0ull,0ull}};
        float sum0 = 0.f, sum1 = 0.f;
        const ulonglong2* kvp = reinterpret_cast<const ulonglong2*>(kvbase);
        #pragma unroll 6
        for (int kq = 0; kq < SEQ; kq++) {
            ulonglong2 P0 = kvp[3*kq];      // (k0,k1),(k2,k3)
            ulonglong2 P1 = kvp[3*kq+1];    // (k4,k5),(v0,v1)
            ulonglong2 P2 = kvp[3*kq+2];    // (v2,v3),(v4,v5)
            #pragma unroll
            for (int j = 0; j < 2; j++) {
                u64 d2 = mul2(qp[j][2], P1.x);
                d2 = fma2(qp[j][1], P0.y, d2);
                d2 = fma2(qp[j][0], P0.x, d2);
                float2 dd = unpack2(d2);
                float e = ex2f(dd.x + dd.y);
                if (j == 0) sum0 += e; else sum1 += e;
                u64 e2 = pack2(e, e);
                o[j][0] = fma2(e2, P1.y, o[j][0]);
                o[j][1] = fma2(e2, P2.x, o[j][1]);
                o[j][2] = fma2(e2, P2.y, o[j][2]);
            }
        }

        // ---- normalize, out proj + ELU + residual ----
        float ov[2][6];
        {
            float inv0 = __fdividef(1.f, sum0);
            float inv1 = __fdividef(1.f, sum1);
            #pragma unroll
            for (int j = 0; j < 2; j++) {
                float inv = (j == 0) ? inv0 : inv1;
                #pragma unroll
                for (int p = 0; p < 3; p++) {
                    float2 d = unpack2(o[j][p]);
                    ov[j][2*p]   = d.x * inv;
                    ov[j][2*p+1] = d.y * inv;
                }
            }
        }
        {
            const float4* w4 = reinterpret_cast<const float4*>(&s_ow[blk][0][0]);
            #pragma unroll
            for (int i = 0; i < 6; i++) {
                float4 a = w4[2*i]; float4 b = w4[2*i+1];
                float bias = s_ob[blk][i];
                #pragma unroll
                for (int j = 0; j < 2; j++) {
                    float acc = bias;
                    acc = fmaf(a.x, ov[j][0], acc); acc = fmaf(a.y, ov[j][1], acc);
                    acc = fmaf(a.z, ov[j][2], acc); acc = fmaf(a.w, ov[j][3], acc);
                    acc = fmaf(b.x, ov[j][4], acc); acc = fmaf(b.y, ov[j][5], acc);
                    h[j][i] += eluf(acc);
                }
            }
        }
    }

    // ---- heads: stage flattened f[324] into (reused) s_kv, then 13 dot products ----
    __syncthreads();                 // last attention reads of s_kv done
    float* f = kvbase;
    #pragma unroll
    for (int j = 0; j < 2; j++)
        #pragma unroll
        for (int d = 0; d < 6; d++) f[(t + j * TPI) * 6 + d] = h[j][d];
    __syncthreads();

    if (t < 13) {
        const float* w = (t < 12) ? (policy_w + t * (SEQ*DIM)) : value_w;
        float acc = (t < 12) ? policy_b[t] : value_b[0];
        const float4* w4 = reinterpret_cast<const float4*>(w);
        const float4* f4 = reinterpret_cast<const float4*>(f);
        #pragma unroll 9
        for (int i = 0; i < (SEQ*DIM)/4; i++) {   // 81 float4s
            float4 a = w4[i]; float4 b = f4[i];
            acc = fmaf(a.x, b.x, acc); acc = fmaf(a.y, b.y, acc);
            acc = fmaf(a.z, b.z, acc); acc = fmaf(a.w, b.w, acc);
        }
        s_lg[g][t] = acc;
    }
    __syncthreads();

    if (t == 12) out[item] = s_lg[g][12];                       // value head
    if (t < 12) {                                               // policy softmax
        float m = s_lg[g][0];
        #pragma unroll
        for (int j = 1; j < 12; j++) m = fmaxf(m, s_lg[g][j]);
        float sum = 0.f;
        #pragma unroll
        for (int j = 0; j < 12; j++) sum += __expf(s_lg[g][j] - m);
        out[BATCH + item*12 + t] = __expf(s_lg[g][t] - m) / sum;
    }
}

extern "C" void kernel_launch(void* const* d_in, const int* in_sizes, int n_in,
                              void* d_out, int out_size) {
    const float* x        = (const float*)d_in[0];
    const float* embed_w  = (const float*)d_in[1];
    const float* embed_b  = (const float*)d_in[2];
    const float* fc1_w    = (const float*)d_in[3];
    const float* fc1_b    = (const float*)d_in[4];
    const float* ln_g     = (const float*)d_in[5];
    const float* ln_b     = (const float*)d_in[6];
    const float* ipw      = (const float*)d_in[7];
    const float* ipb      = (const float*)d_in[8];
    const float* outw     = (const float*)d_in[9];
    const float* outb     = (const float*)d_in[10];
    const float* value_w  = (const float*)d_in[11];
    const float* value_b  = (const float*)d_in[12];
    const float* policy_w = (const float*)d_in[13];
    const float* policy_b = (const float*)d_in[14];
    float* out = (float*)d_out;

    rubik_kernel<<<BATCH / GG, TPB>>>(x, embed_w, embed_b, fc1_w, fc1_b,
                                      ln_g, ln_b, ipw, ipb, outw, outb,
                                      value_w, value_b, policy_w, policy_b, out);
}